// round 2
// baseline (speedup 1.0000x reference)
#include <cuda_runtime.h>
#include <math.h>

#define Nn 8192
#define Dd 512
#define Cc 100

// ---- scratch (no allocations allowed) ----
__device__ float g_s[Nn];      // 1/max(||x_i||, 1e-8)
__device__ float g_w[Nn];      // max softmax prob
__device__ int   g_cls[Nn];    // argmax class
__device__ float g_cnt[Cc];    // per-class counts
__device__ float g_G[Dd * Dd]; // G = sum_i s_i x_i x_i^T (symmetric)
__device__ float g_A[Cc * Dd]; // sum_{cls=c} w_i s_i x_i
__device__ float g_B[Cc * Dd]; // sum_{cls=c} w_i x_i

// ---------------- zero scratch ----------------
__global__ void k_zero() {
    int t = blockIdx.x * blockDim.x + threadIdx.x;
    int stride = gridDim.x * blockDim.x;
    for (int i = t; i < Dd * Dd; i += stride) g_G[i] = 0.f;
    for (int i = t; i < Cc * Dd; i += stride) { g_A[i] = 0.f; g_B[i] = 0.f; }
    for (int i = t; i < Cc; i += stride) g_cnt[i] = 0.f;
}

// ---------------- per-row stats: inv-norm, max softmax, argmax ----------------
__global__ void k_rowstats(const float* __restrict__ x,
                           const float* __restrict__ logits) {
    int row = blockIdx.x;
    int t = threadIdx.x;            // 128 threads
    __shared__ float red[128];
    __shared__ int   redi[128];

    // ||x_row||^2
    const float* xr = x + (size_t)row * Dd;
    float s2 = 0.f;
    #pragma unroll
    for (int i = t; i < Dd; i += 128) { float v = xr[i]; s2 += v * v; }
    red[t] = s2; __syncthreads();
    for (int o = 64; o > 0; o >>= 1) {
        if (t < o) red[t] += red[t + o];
        __syncthreads();
    }
    float norm2 = red[0];
    __syncthreads();

    // logits max + argmax (first index on tie)
    const float* lr = logits + (size_t)row * Cc;
    float lv = (t < Cc) ? lr[t] : -3.402823466e38f;
    red[t] = lv; redi[t] = t; __syncthreads();
    for (int o = 64; o > 0; o >>= 1) {
        if (t < o) {
            float ov = red[t + o]; int oi = redi[t + o];
            if (ov > red[t] || (ov == red[t] && oi < redi[t])) { red[t] = ov; redi[t] = oi; }
        }
        __syncthreads();
    }
    float lmax = red[0];
    int cls = redi[0];
    __syncthreads();

    // sum exp(l - lmax)
    float e = (t < Cc) ? expf(lv - lmax) : 0.f;
    red[t] = e; __syncthreads();
    for (int o = 64; o > 0; o >>= 1) {
        if (t < o) red[t] += red[t + o];
        __syncthreads();
    }
    if (t == 0) {
        g_s[row]   = 1.f / fmaxf(sqrtf(norm2), 1e-8f);
        g_w[row]   = 1.f / red[0];     // softmax value at argmax
        g_cls[row] = cls;
        atomicAdd(&g_cnt[cls], 1.f);
    }
}

// ---------------- G = sum_i s_i x_i x_i^T  (512x512, upper-tri tiles, split-K) --
#define TK 32
#define SPLITK 8
#define NTILES 8                      // 512/64
#define NTRI   (NTILES * (NTILES + 1) / 2)   // 36
__global__ void k_gram(const float* __restrict__ x) {
    __shared__ float As[TK][64];
    __shared__ float Bs[TK][64];

    // decode linear upper-triangular tile index -> (ti, tj), ti <= tj
    int t = blockIdx.x;
    int ti = 0, rem = t;
    while (rem >= NTILES - ti) { rem -= NTILES - ti; ti++; }
    int tj = ti + rem;

    int a0 = ti * 64;
    int b0 = tj * 64;
    int k0   = blockIdx.z * (Nn / SPLITK);
    int kend = k0 + (Nn / SPLITK);
    int tid = threadIdx.x;              // 256
    int tx = tid & 15, ty = tid >> 4;   // 16x16 threads, 4x4 per thread

    float acc[4][4] = {};

    for (int kb = k0; kb < kend; kb += TK) {
        #pragma unroll
        for (int p = 0; p < 2; p++) {
            int idx = p * 256 + tid;
            int kk = idx >> 4;
            int c4 = (idx & 15) * 4;
            int r = kb + kk;
            float sv = g_s[r];
            float4 va = *(const float4*)(x + (size_t)r * Dd + a0 + c4);
            va.x *= sv; va.y *= sv; va.z *= sv; va.w *= sv;
            *(float4*)&As[kk][c4] = va;
            float4 vb = *(const float4*)(x + (size_t)r * Dd + b0 + c4);
            *(float4*)&Bs[kk][c4] = vb;
        }
        __syncthreads();
        #pragma unroll
        for (int kk = 0; kk < TK; kk++) {
            float4 av = *(float4*)&As[kk][ty * 4];
            float4 bv = *(float4*)&Bs[kk][tx * 4];
            float a[4] = {av.x, av.y, av.z, av.w};
            float b[4] = {bv.x, bv.y, bv.z, bv.w};
            #pragma unroll
            for (int i = 0; i < 4; i++)
                #pragma unroll
                for (int j = 0; j < 4; j++)
                    acc[i][j] += a[i] * b[j];
        }
        __syncthreads();
    }

    #pragma unroll
    for (int i = 0; i < 4; i++)
        #pragma unroll
        for (int j = 0; j < 4; j++)
            atomicAdd(&g_G[(size_t)(a0 + ty * 4 + i) * Dd + b0 + tx * 4 + j], acc[i][j]);
}

// ---------------- mirror lower triangle from upper ----------------
__global__ void k_symm() {
    int t = blockIdx.x * blockDim.x + threadIdx.x;
    int stride = gridDim.x * blockDim.x;
    for (int i = t; i < Dd * Dd; i += stride) {
        int a = i / Dd, b = i % Dd;
        if (a > b) g_G[i] = g_G[(size_t)b * Dd + a];
    }
}

// ---------------- per-class weighted sums A, B (smem aggregation) ----------------
#define RSPLIT 8
__global__ void k_scatter(const float* __restrict__ x) {
    __shared__ float sA[Cc][32];
    __shared__ float sB[Cc][32];
    int c0 = blockIdx.x * 32;             // D-chunk
    int r0 = blockIdx.y * (Nn / RSPLIT);  // row chunk (1024 rows)
    int tid = threadIdx.x;                // 256
    int tx = tid & 31, ty = tid >> 5;     // 8 rows per pass

    for (int i = tid; i < Cc * 32; i += 256) {
        (&sA[0][0])[i] = 0.f;
        (&sB[0][0])[i] = 0.f;
    }
    __syncthreads();

    int rend = r0 + (Nn / RSPLIT);
    for (int r = r0 + ty; r < rend; r += 8) {
        int   c  = g_cls[r];
        float w  = g_w[r];
        float ws = w * g_s[r];
        float xv = x[(size_t)r * Dd + c0 + tx];
        atomicAdd(&sA[c][tx], ws * xv);
        atomicAdd(&sB[c][tx], w  * xv);
    }
    __syncthreads();

    for (int i = tid; i < Cc * 32; i += 256) {
        int cl = i >> 5, col = i & 31;
        atomicAdd(&g_A[(size_t)cl * Dd + c0 + col], sA[cl][col]);
        atomicAdd(&g_B[(size_t)cl * Dd + c0 + col], sB[cl][col]);
    }
}

// ---------------- prototypes = (A @ G + B) / counts ----------------
__global__ void k_proto(float* __restrict__ out) {
    int c = blockIdx.x;       // class
    int tid = threadIdx.x;    // 256, each thread handles d = tid and tid+256
    __shared__ float sA[Dd];
    for (int i = tid; i < Dd; i += 256) sA[i] = g_A[(size_t)c * Dd + i];
    __syncthreads();

    float acc0 = 0.f, acc1 = 0.f;
    #pragma unroll 8
    for (int k = 0; k < Dd; k++) {
        float a = sA[k];
        acc0 += a * g_G[(size_t)k * Dd + tid];
        acc1 += a * g_G[(size_t)k * Dd + tid + 256];
    }
    float cnt = g_cnt[c];
    float inv = 1.f / fmaxf(cnt, 1.f);
    float p0 = (cnt > 0.f) ? (acc0 + g_B[(size_t)c * Dd + tid])        * inv : 0.f;
    float p1 = (cnt > 0.f) ? (acc1 + g_B[(size_t)c * Dd + tid + 256])  * inv : 0.f;
    out[(size_t)c * Dd + tid]       = p0;
    out[(size_t)c * Dd + tid + 256] = p1;
}

// ---------------- inter_class_matrix[i,j,:] = P[j] - P[i] ----------------
__global__ void k_inter(const float* __restrict__ P, float* __restrict__ out) {
    const int D4 = Dd / 4;
    long total = (long)Cc * Cc * D4;
    long stride = (long)gridDim.x * blockDim.x;
    for (long t = (long)blockIdx.x * blockDim.x + threadIdx.x; t < total; t += stride) {
        int d4 = (int)(t % D4);
        long ij = t / D4;
        int j = (int)(ij % Cc);
        int i = (int)(ij / Cc);
        float4 pj = *(const float4*)(P + (size_t)j * Dd + d4 * 4);
        float4 pi = *(const float4*)(P + (size_t)i * Dd + d4 * 4);
        float4 o;
        o.x = pj.x - pi.x; o.y = pj.y - pi.y;
        o.z = pj.z - pi.z; o.w = pj.w - pi.w;
        ((float4*)out)[t] = o;
    }
}

extern "C" void kernel_launch(void* const* d_in, const int* in_sizes, int n_in,
                              void* d_out, int out_size) {
    const float* x      = (const float*)d_in[0];   // [8192, 512]
    const float* logits = (const float*)d_in[1];   // [8192, 100]
    float* out = (float*)d_out;                    // [C*D prototypes | C*C*D inter]

    k_zero<<<256, 256>>>();
    k_rowstats<<<Nn, 128>>>(x, logits);
    k_gram<<<dim3(NTRI, 1, SPLITK), 256>>>(x);
    k_symm<<<512, 256>>>();
    k_scatter<<<dim3(Dd / 32, RSPLIT), 256>>>(x);
    k_proto<<<Cc, 256>>>(out);
    k_inter<<<2560, 256>>>(out, out + (size_t)Cc * Dd);
}